// round 7
// baseline (speedup 1.0000x reference)
#include <cuda_runtime.h>
#include <math.h>

// Fixed problem shapes:
// feat0 [2,256,200,200] f32, feat1 [2,256,100,100], feat2 [2,256,50,50],
// feat3 [2,256,25,25], boxes [2,256,4] f32 -> out [512,256,7,7] f32.
#define KROIS   512
#define NC      256
#define OUTHW   7
#define NBINS   49
#define WARPS   8                 // warps per block
#define GRPS    4                 // channel-groups per roi
#define CPB     (NC / GRPS)       // 64 channels per block
#define CPW     (CPB / WARPS)     // 8 channels per warp
#define NPAIR   (CPW / 2)         // 4 pair-iterations per warp
#define TSTRIDE 28                // 7*28 floats per channel = 49 aligned float4

__device__ __forceinline__ void prep_coord(float c, int size,
                                           int& lo, int& hi, float& l, float& h)
{
    c = fmaxf(c, 0.0f);
    lo = (int)c;
    if (lo >= size - 1) { lo = size - 1; hi = size - 1; }
    else                { hi = lo + 1; }
    l = c - (float)lo;
    h = 1.0f - l;
}

__global__ void __launch_bounds__(256)
roi_align_8ch_kernel(const float* __restrict__ f0,
                     const float* __restrict__ f1,
                     const float* __restrict__ f2,
                     const float* __restrict__ f3,
                     const float* __restrict__ boxes,
                     float* __restrict__ out)
{
    __shared__ float  s_temp[WARPS][2][OUTHW * TSTRIDE];   // 12.25 KB
    __shared__ int4   s_yoff[OUTHW];
    __shared__ float4 s_yw[OUTHW];
    __shared__ float  s_f[4];
    __shared__ int    s_i[2];

    const int k   = blockIdx.x >> 2;          // roi  (GRPS = 4)
    const int grp = blockIdx.x & (GRPS - 1);
    const int tid = threadIdx.x;

    // ---- per-roi scalars (thread 0 only) ----
    if (tid == 0) {
        const float* bx = boxes + k * 4;
        float x1 = bx[0], y1 = bx[1], x2 = bx[2], y2 = bx[3];

        float area = (x2 - x1) * (y2 - y1);
        float s    = sqrtf(area);
        float lvl  = floorf(4.0f + log2f(s / 224.0f) + 1e-6f);
        lvl = fminf(fmaxf(lvl, 2.0f), 5.0f);
        int level = (int)lvl - 2;

        const float scales[4] = {0.25f, 0.125f, 0.0625f, 0.03125f};
        const int   dims[4]   = {200, 100, 50, 25};
        float sc = scales[level];
        int   W  = dims[level];

        float x1s = x1 * sc, y1s = y1 * sc;
        float x2s = x2 * sc, y2s = y2 * sc;

        s_f[0] = x1s;
        s_f[1] = y1s;
        s_f[2] = fmaxf(x2s - x1s, 1.0f) / (float)OUTHW;
        s_f[3] = fmaxf(y2s - y1s, 1.0f) / (float)OUTHW;
        s_i[0] = level;
        s_i[1] = W;
    }
    __syncthreads();

    const int   level = s_i[0];
    const int   W     = s_i[1];
    const float x1s   = s_f[0];
    const float y1s   = s_f[1];
    const float bin_w = s_f[2];
    const float bin_h = s_f[3];

    // ---- y tables (threads 0-6) ----
    if (tid < OUTHW) {
        int p = tid;
        float half = bin_h * 0.5f;
        int lo0, hi0, lo1, hi1; float l0, h0, l1, h1;
        prep_coord(y1s + (float)p * bin_h + 0.5f * half, W, lo0, hi0, l0, h0);
        prep_coord(y1s + (float)p * bin_h + 1.5f * half, W, lo1, hi1, l1, h1);
        s_yoff[p] = make_int4(lo0 * W, hi0 * W, lo1 * W, hi1 * W);
        s_yw[p]   = make_float4(h0, l0, h1, l1);
    }
    __syncthreads();

    const int warp = tid >> 5;
    const int lane = tid & 31;
    const int c0   = grp * CPB + warp * CPW;    // first of CPW adjacent channels
    const int b    = k >> 8;

    // ---- per-lane x corner: j = 4*pw + 2*ix + corner (lanes 28-31 mirror 27) ----
    const int j      = (lane < 28) ? lane : 27;
    const int si     = j >> 1;
    const int corner = j & 1;
    const int pwj    = si >> 1;
    const int ixj    = si & 1;

    float half_bw = bin_w * 0.5f;
    int xlo, xhi; float xl, xh;
    prep_coord(x1s + (float)pwj * bin_w + ((float)ixj + 0.5f) * half_bw, W,
               xlo, xhi, xl, xh);
    const int   xc = corner ? xhi : xlo;
    const float xw = 0.25f * (corner ? xl : xh);

    const float* feat;
    switch (level) {
        case 0:  feat = f0; break;
        case 1:  feat = f1; break;
        case 2:  feat = f2; break;
        default: feat = f3; break;
    }
    const int plane = W * W;
    const float* __restrict__ pb0 =
        feat + (size_t)((b * NC + c0) * W) * (size_t)W + xc;

    // y row offsets + weights cached in registers
    int4 ro[OUTHW];
    float4 yw[OUTHW];
    #pragma unroll
    for (int ph = 0; ph < OUTHW; ph++) { ro[ph] = s_yoff[ph]; yw[ph] = s_yw[ph]; }

    size_t obase = (size_t)(k * NC + c0) * NBINS;
    const float4* __restrict__ t40 = (const float4*)s_temp[warp][0];
    const float4* __restrict__ t41 = (const float4*)s_temp[warp][1];

    #pragma unroll 1
    for (int pp = 0; pp < NPAIR; pp++) {
        const float* __restrict__ p0 = pb0;
        const float* __restrict__ p1 = pb0 + plane;

        // ---- phase A: all 56 loads (2 channels x 28) batched ----
        float v[2][OUTHW][4];
        #pragma unroll
        for (int ph = 0; ph < OUTHW; ph++) {
            v[0][ph][0] = __ldg(p0 + ro[ph].x);
            v[0][ph][1] = __ldg(p0 + ro[ph].y);
            v[0][ph][2] = __ldg(p0 + ro[ph].z);
            v[0][ph][3] = __ldg(p0 + ro[ph].w);
            v[1][ph][0] = __ldg(p1 + ro[ph].x);
            v[1][ph][1] = __ldg(p1 + ro[ph].y);
            v[1][ph][2] = __ldg(p1 + ro[ph].z);
            v[1][ph][3] = __ldg(p1 + ro[ph].w);
        }

        #pragma unroll
        for (int ch = 0; ch < 2; ch++) {
            float* __restrict__ tw = s_temp[warp][ch];
            #pragma unroll
            for (int ph = 0; ph < OUTHW; ph++) {
                float a = yw[ph].x * v[ch][ph][0] + yw[ph].y * v[ch][ph][1]
                        + yw[ph].z * v[ch][ph][2] + yw[ph].w * v[ch][ph][3];
                if (lane < 28) tw[ph * TSTRIDE + j] = a * xw;
            }
        }
        __syncwarp();

        // ---- phase B: one LDS.128 per bin, 98 contiguous stores per warp ----
        #pragma unroll
        for (int o = lane; o < 2 * NBINS; o += 32) {
            float4 t = (o < NBINS) ? t40[o] : t41[o - NBINS];
            out[obase + o] = (t.x + t.y) + (t.z + t.w);
        }
        __syncwarp();

        pb0 += 2 * plane;
        obase += 2 * NBINS;
    }
}

extern "C" void kernel_launch(void* const* d_in, const int* in_sizes, int n_in,
                              void* d_out, int out_size)
{
    const float* f0    = (const float*)d_in[0];
    const float* f1    = (const float*)d_in[1];
    const float* f2    = (const float*)d_in[2];
    const float* f3    = (const float*)d_in[3];
    const float* boxes = (const float*)d_in[4];
    float* out = (float*)d_out;

    const int blocks = KROIS * GRPS;   // 512 * 4 = 2048
    roi_align_8ch_kernel<<<blocks, 256>>>(f0, f1, f2, f3, boxes, out);
}

// round 8
// speedup vs baseline: 1.2487x; 1.2487x over previous
#include <cuda_runtime.h>
#include <math.h>

// Fixed problem shapes:
// feat0 [2,256,200,200] f32, feat1 [2,256,100,100], feat2 [2,256,50,50],
// feat3 [2,256,25,25], boxes [2,256,4] f32 -> out [512,256,7,7] f32.
#define KROIS   512
#define NC      256
#define OUTHW   7
#define NBINS   49
#define WARPS   8               // warps per block
#define CPW     2               // channels per warp
#define CPB     (WARPS * CPW)   // 16 channels per block
#define GRPS    (NC / CPB)      // 16 channel-groups per roi
#define TSTRIDE 28              // 7*28 floats = 49 aligned float4 per channel

__device__ __forceinline__ void prep_coord(float c, int size,
                                           int& lo, int& hi, float& l, float& h)
{
    c = fmaxf(c, 0.0f);
    lo = (int)c;
    if (lo >= size - 1) { lo = size - 1; hi = size - 1; }
    else                { hi = lo + 1; }
    l = c - (float)lo;
    h = 1.0f - l;
}

__global__ void __launch_bounds__(256, 6)
roi_align_2ch_v2_kernel(const float* __restrict__ f0,
                        const float* __restrict__ f1,
                        const float* __restrict__ f2,
                        const float* __restrict__ f3,
                        const float* __restrict__ boxes,
                        float* __restrict__ out)
{
    __shared__ float  s_temp[WARPS][CPW][OUTHW * TSTRIDE];  // 12.25 KB
    __shared__ int4   s_yoff[OUTHW];
    __shared__ float4 s_yw[OUTHW];
    __shared__ float  s_f[4];
    __shared__ int    s_i[2];

    const int k   = blockIdx.x >> 4;          // roi  (GRPS = 16)
    const int grp = blockIdx.x & (GRPS - 1);
    const int tid = threadIdx.x;

    // ---- per-roi scalars (thread 0 only) ----
    if (tid == 0) {
        const float* bx = boxes + k * 4;
        float x1 = bx[0], y1 = bx[1], x2 = bx[2], y2 = bx[3];

        float area = (x2 - x1) * (y2 - y1);
        float s    = sqrtf(area);
        float lvl  = floorf(4.0f + log2f(s / 224.0f) + 1e-6f);
        lvl = fminf(fmaxf(lvl, 2.0f), 5.0f);
        int level = (int)lvl - 2;

        const float scales[4] = {0.25f, 0.125f, 0.0625f, 0.03125f};
        const int   dims[4]   = {200, 100, 50, 25};
        float sc = scales[level];
        int   W  = dims[level];

        float x1s = x1 * sc, y1s = y1 * sc;
        float x2s = x2 * sc, y2s = y2 * sc;

        s_f[0] = x1s;
        s_f[1] = y1s;
        s_f[2] = fmaxf(x2s - x1s, 1.0f) / (float)OUTHW;
        s_f[3] = fmaxf(y2s - y1s, 1.0f) / (float)OUTHW;
        s_i[0] = level;
        s_i[1] = W;
    }
    __syncthreads();

    const int   level = s_i[0];
    const int   W     = s_i[1];
    const float x1s   = s_f[0];
    const float y1s   = s_f[1];
    const float bin_w = s_f[2];
    const float bin_h = s_f[3];

    // ---- y tables (threads 0-6) ----
    if (tid < OUTHW) {
        int p = tid;
        float half = bin_h * 0.5f;
        int lo0, hi0, lo1, hi1; float l0, h0, l1, h1;
        prep_coord(y1s + (float)p * bin_h + 0.5f * half, W, lo0, hi0, l0, h0);
        prep_coord(y1s + (float)p * bin_h + 1.5f * half, W, lo1, hi1, l1, h1);
        s_yoff[p] = make_int4(lo0 * W, hi0 * W, lo1 * W, hi1 * W);
        s_yw[p]   = make_float4(h0, l0, h1, l1);
    }
    __syncthreads();

    const int warp = tid >> 5;
    const int lane = tid & 31;
    const int c0   = grp * CPB + warp * CPW;    // first of 2 adjacent channels
    const int b    = k >> 8;

    // ---- per-lane x corner: j = 4*pw + 2*ix + corner (lanes 28-31 mirror 27) ----
    const int j      = (lane < 28) ? lane : 27;
    const int si     = j >> 1;
    const int corner = j & 1;
    const int pwj    = si >> 1;
    const int ixj    = si & 1;

    float half_bw = bin_w * 0.5f;
    int xlo, xhi; float xl, xh;
    prep_coord(x1s + (float)pwj * bin_w + ((float)ixj + 0.5f) * half_bw, W,
               xlo, xhi, xl, xh);
    const int   xc = corner ? xhi : xlo;
    const float xw = 0.25f * (corner ? xl : xh);

    const float* feat;
    switch (level) {
        case 0:  feat = f0; break;
        case 1:  feat = f1; break;
        case 2:  feat = f2; break;
        default: feat = f3; break;
    }
    const int plane = W * W;
    const float* __restrict__ pb =
        feat + (size_t)((b * NC + c0) * W) * (size_t)W + xc;

    // ---- phase A: per channel, batch 28 loads then FMA+store (regs ~ v[28]) ----
    #pragma unroll
    for (int ch = 0; ch < CPW; ch++) {
        const float* __restrict__ p = pb + ch * plane;
        float v[OUTHW][4];
        #pragma unroll
        for (int ph = 0; ph < OUTHW; ph++) {
            int4 ro = s_yoff[ph];
            v[ph][0] = __ldg(p + ro.x);
            v[ph][1] = __ldg(p + ro.y);
            v[ph][2] = __ldg(p + ro.z);
            v[ph][3] = __ldg(p + ro.w);
        }
        float* __restrict__ tw = s_temp[warp][ch];
        #pragma unroll
        for (int ph = 0; ph < OUTHW; ph++) {
            float4 yw = s_yw[ph];
            float a = yw.x * v[ph][0] + yw.y * v[ph][1]
                    + yw.z * v[ph][2] + yw.w * v[ph][3];
            if (lane < 28) tw[ph * TSTRIDE + j] = a * xw;
        }
    }
    __syncwarp();

    // ---- phase B: one LDS.128 per bin, 98 contiguous stores per warp ----
    const float4* __restrict__ t40 = (const float4*)s_temp[warp][0];
    const float4* __restrict__ t41 = (const float4*)s_temp[warp][1];
    const size_t obase = (size_t)(k * NC + c0) * NBINS;
    #pragma unroll
    for (int o = lane; o < CPW * NBINS; o += 32) {
        float4 t = (o < NBINS) ? t40[o] : t41[o - NBINS];
        out[obase + o] = (t.x + t.y) + (t.z + t.w);
    }
}

extern "C" void kernel_launch(void* const* d_in, const int* in_sizes, int n_in,
                              void* d_out, int out_size)
{
    const float* f0    = (const float*)d_in[0];
    const float* f1    = (const float*)d_in[1];
    const float* f2    = (const float*)d_in[2];
    const float* f3    = (const float*)d_in[3];
    const float* boxes = (const float*)d_in[4];
    float* out = (float*)d_out;

    const int blocks = KROIS * GRPS;   // 512 * 16 = 8192
    roi_align_2ch_v2_kernel<<<blocks, 256>>>(f0, f1, f2, f3, boxes, out);
}

// round 9
// speedup vs baseline: 1.2710x; 1.0178x over previous
#include <cuda_runtime.h>
#include <math.h>

// Fixed problem shapes:
// feat0 [2,256,200,200] f32, feat1 [2,256,100,100], feat2 [2,256,50,50],
// feat3 [2,256,25,25], boxes [2,256,4] f32 -> out [512,256,7,7] f32.
#define KROIS   512
#define NC      256
#define OUTHW   7
#define NBINS   49
#define WARPS   8               // warps per block
#define CPW     4               // channels per warp (2 pair-iterations)
#define CPB     (WARPS * CPW)   // 32 channels per block
#define GRPS    (NC / CPB)      // 8 channel-groups per roi
#define TSTRIDE 28              // 7*28 floats = 49 aligned float4 per channel

__device__ __forceinline__ void prep_coord(float c, int size,
                                           int& lo, int& hi, float& l, float& h)
{
    c = fmaxf(c, 0.0f);
    lo = (int)c;
    if (lo >= size - 1) { lo = size - 1; hi = size - 1; }
    else                { hi = lo + 1; }
    l = c - (float)lo;
    h = 1.0f - l;
}

__global__ void __launch_bounds__(256, 6)
roi_align_4ch_kernel(const float* __restrict__ f0,
                     const float* __restrict__ f1,
                     const float* __restrict__ f2,
                     const float* __restrict__ f3,
                     const float* __restrict__ boxes,
                     float* __restrict__ out)
{
    __shared__ float  s_temp[WARPS][2][OUTHW * TSTRIDE];  // 12.25 KB
    __shared__ int4   s_yoff[OUTHW];
    __shared__ float4 s_yw[OUTHW];
    __shared__ float  s_f[4];
    __shared__ int    s_i[2];

    const int k   = blockIdx.x >> 3;          // roi  (GRPS = 8)
    const int grp = blockIdx.x & (GRPS - 1);
    const int tid = threadIdx.x;

    // ---- per-roi scalars (thread 0 only) ----
    if (tid == 0) {
        const float4 bx = __ldg((const float4*)boxes + k);
        float x1 = bx.x, y1 = bx.y, x2 = bx.z, y2 = bx.w;

        float area = (x2 - x1) * (y2 - y1);
        float s    = sqrtf(area);
        float lvl  = floorf(4.0f + log2f(s / 224.0f) + 1e-6f);
        lvl = fminf(fmaxf(lvl, 2.0f), 5.0f);
        int level = (int)lvl - 2;

        const float scales[4] = {0.25f, 0.125f, 0.0625f, 0.03125f};
        const int   dims[4]   = {200, 100, 50, 25};
        float sc = scales[level];
        int   W  = dims[level];

        float x1s = x1 * sc, y1s = y1 * sc;
        float x2s = x2 * sc, y2s = y2 * sc;

        s_f[0] = x1s;
        s_f[1] = y1s;
        s_f[2] = fmaxf(x2s - x1s, 1.0f) / (float)OUTHW;
        s_f[3] = fmaxf(y2s - y1s, 1.0f) / (float)OUTHW;
        s_i[0] = level;
        s_i[1] = W;
    }
    __syncthreads();

    const int   level = s_i[0];
    const int   W     = s_i[1];
    const float x1s   = s_f[0];
    const float y1s   = s_f[1];
    const float bin_w = s_f[2];
    const float bin_h = s_f[3];

    // ---- y tables (threads 0-6) ----
    if (tid < OUTHW) {
        int p = tid;
        float half = bin_h * 0.5f;
        int lo0, hi0, lo1, hi1; float l0, h0, l1, h1;
        prep_coord(y1s + (float)p * bin_h + 0.5f * half, W, lo0, hi0, l0, h0);
        prep_coord(y1s + (float)p * bin_h + 1.5f * half, W, lo1, hi1, l1, h1);
        s_yoff[p] = make_int4(lo0 * W, hi0 * W, lo1 * W, hi1 * W);
        s_yw[p]   = make_float4(h0, l0, h1, l1);
    }
    __syncthreads();

    const int warp = tid >> 5;
    const int lane = tid & 31;
    const int c0   = grp * CPB + warp * CPW;    // first of CPW adjacent channels
    const int b    = k >> 8;

    // ---- per-lane x corner: j = 4*pw + 2*ix + corner (lanes 28-31 mirror 27) ----
    const int j      = (lane < 28) ? lane : 27;
    const int si     = j >> 1;
    const int corner = j & 1;
    const int pwj    = si >> 1;
    const int ixj    = si & 1;

    float half_bw = bin_w * 0.5f;
    int xlo, xhi; float xl, xh;
    prep_coord(x1s + (float)pwj * bin_w + ((float)ixj + 0.5f) * half_bw, W,
               xlo, xhi, xl, xh);
    const int   xc = corner ? xhi : xlo;
    const float xw = 0.25f * (corner ? xl : xh);

    const float* feat;
    switch (level) {
        case 0:  feat = f0; break;
        case 1:  feat = f1; break;
        case 2:  feat = f2; break;
        default: feat = f3; break;
    }
    const int plane = W * W;
    const float* __restrict__ pb =
        feat + (size_t)((b * NC + c0) * W) * (size_t)W + xc;

    const float4* __restrict__ t40 = (const float4*)s_temp[warp][0];
    const float4* __restrict__ t41 = (const float4*)s_temp[warp][1];
    size_t obase = (size_t)(k * NC + c0) * NBINS;

    #pragma unroll 1
    for (int pp = 0; pp < CPW / 2; pp++) {
        // ---- phase A: per channel, batch 28 loads then FMA+store ----
        #pragma unroll
        for (int ch = 0; ch < 2; ch++) {
            const float* __restrict__ p = pb + ch * plane;
            float v[OUTHW][4];
            #pragma unroll
            for (int ph = 0; ph < OUTHW; ph++) {
                int4 ro = s_yoff[ph];
                v[ph][0] = __ldg(p + ro.x);
                v[ph][1] = __ldg(p + ro.y);
                v[ph][2] = __ldg(p + ro.z);
                v[ph][3] = __ldg(p + ro.w);
            }
            float* __restrict__ tw = s_temp[warp][ch];
            #pragma unroll
            for (int ph = 0; ph < OUTHW; ph++) {
                float4 yw = s_yw[ph];
                float a = yw.x * v[ph][0] + yw.y * v[ph][1]
                        + yw.z * v[ph][2] + yw.w * v[ph][3];
                if (lane < 28) tw[ph * TSTRIDE + j] = a * xw;
            }
        }
        __syncwarp();

        // ---- phase B: one LDS.128 per bin, 98 contiguous stores per warp ----
        #pragma unroll
        for (int o = lane; o < 2 * NBINS; o += 32) {
            float4 t = (o < NBINS) ? t40[o] : t41[o - NBINS];
            out[obase + o] = (t.x + t.y) + (t.z + t.w);
        }
        __syncwarp();

        pb    += 2 * plane;
        obase += 2 * NBINS;
    }
}

extern "C" void kernel_launch(void* const* d_in, const int* in_sizes, int n_in,
                              void* d_out, int out_size)
{
    const float* f0    = (const float*)d_in[0];
    const float* f1    = (const float*)d_in[1];
    const float* f2    = (const float*)d_in[2];
    const float* f3    = (const float*)d_in[3];
    const float* boxes = (const float*)d_in[4];
    float* out = (float*)d_out;

    const int blocks = KROIS * GRPS;   // 512 * 8 = 4096
    roi_align_4ch_kernel<<<blocks, 256>>>(f0, f1, f2, f3, boxes, out);
}